// round 1
// baseline (speedup 1.0000x reference)
#include <cuda_runtime.h>

#define BATCH 4
#define NPTS  16384
#define KNN   16
#define CIN   32
#define D2    32
#define DD    64
#define DOUT  128
#define P_TOT (BATCH*NPTS)
#define ST    20   // x-tile row stride in floats (16B-aligned rows, low STS conflicts)
#define WPB   8    // warps per block for kB/kC

// ---- scratch (no cudaMalloc allowed) ----
__device__ float g_fpc  [P_TOT*CIN];   // [B,N,32] relu(mlp1 @ feature)
__device__ float g_featT[P_TOT*CIN];   // [B,N,32] transposed input feature
__device__ float g_fagg [P_TOT*D2];    // [B,N,32] stage-1 attention output
__device__ float g_tmp  [(size_t)P_TOT*DOUT]; // [B,N,128] pre-transpose output

// ============================================================
// Kernel A: f_pc = relu((mlp1_W @ feature)*s + b) and feature transpose
// ============================================================
__global__ void __launch_bounds__(256) kA(const float* __restrict__ feature,
                                          const float* __restrict__ W,
                                          const float* __restrict__ s,
                                          const float* __restrict__ bb)
{
    __shared__ float Wt[CIN*CIN];       // Wt[j*32+o] = W[o*32+j]
    __shared__ float col[WPB][CIN];
    int tid = threadIdx.x;
    for (int i = tid; i < CIN*CIN; i += 256) {
        int o = i / CIN, j = i % CIN;
        Wt[j*CIN + o] = W[i];
    }
    __syncthreads();
    int lane = tid & 31, w = tid >> 5;
    float sv = s[lane], bv = bb[lane];
    int warpId = blockIdx.x * WPB + w;
    int nwarps = gridDim.x * WPB;
    for (int p = warpId; p < P_TOT; p += nwarps) {
        int b = p >> 14, n = p & (NPTS-1);
        float f = feature[((size_t)b*CIN + lane)*NPTS + n];
        g_featT[(size_t)p*CIN + lane] = f;
        col[w][lane] = f;
        __syncwarp();
        float acc = 0.f;
        #pragma unroll
        for (int j = 0; j < CIN; j++) acc += Wt[j*CIN + lane] * col[w][j];
        g_fpc[(size_t)p*CIN + lane] = fmaxf(acc*sv + bv, 0.f);
        __syncwarp();
    }
}

// softmax over 16 + weighted aggregate, all in registers
__device__ __forceinline__ float softagg(const float* a, const float* v) {
    float m = a[0];
    #pragma unroll
    for (int k = 1; k < 16; k++) m = fmaxf(m, a[k]);
    float se = 0.f, r = 0.f;
    #pragma unroll
    for (int k = 0; k < 16; k++) {
        float e = __expf(a[k] - m);
        se += e; r += e * v[k];
    }
    return r / se;
}

// compute bb1 (rel-pos encoding conv) for one point; lane = output channel.
// Also returns neighbor indices via ids[].
__device__ __forceinline__ void bb1_compute(const float* __restrict__ xyzB, int n,
                                            const int* __restrict__ ip,
                                            const float* w10, float bs, float bbv,
                                            int* ids, float* fx)
{
    int4 i0 = ((const int4*)ip)[0];
    int4 i1 = ((const int4*)ip)[1];
    int4 i2 = ((const int4*)ip)[2];
    int4 i3 = ((const int4*)ip)[3];
    ids[0]=i0.x; ids[1]=i0.y; ids[2]=i0.z; ids[3]=i0.w;
    ids[4]=i1.x; ids[5]=i1.y; ids[6]=i1.z; ids[7]=i1.w;
    ids[8]=i2.x; ids[9]=i2.y; ids[10]=i2.z; ids[11]=i2.w;
    ids[12]=i3.x; ids[13]=i3.y; ids[14]=i3.z; ids[15]=i3.w;
    float cx = xyzB[n*3], cy = xyzB[n*3+1], cz = xyzB[n*3+2];
    float cpart = w10[4]*cx + w10[5]*cy + w10[6]*cz;
    #pragma unroll
    for (int k = 0; k < 16; k++) {
        int id = ids[k];
        float nx = xyzB[id*3], ny = xyzB[id*3+1], nz = xyzB[id*3+2];
        float rx = cx-nx, ry = cy-ny, rz = cz-nz;
        float d = sqrtf(rx*rx + ry*ry + rz*rz);
        float acc = cpart
                  + w10[0]*d  + w10[1]*rx + w10[2]*ry + w10[3]*rz
                  + w10[7]*nx + w10[8]*ny + w10[9]*nz;
        fx[k] = fmaxf(acc*bs + bbv, 0.f);
    }
}

// ============================================================
// Kernel B: stage-1 attention pooling -> g_fagg [B,N,32]
// dyn smem: fc1T[4096] | a1T[2048] | s1v[32] | b1v[32] | xb[WPB*64*ST]
// ============================================================
#define SMEM_B_FLOATS (4096 + 2048 + 32 + 32 + WPB*DD*ST)

__global__ void __launch_bounds__(256) kB(
    const float* __restrict__ xyz, const int* __restrict__ nidx,
    const float* __restrict__ bb1W, const float* __restrict__ bb1s, const float* __restrict__ bb1b,
    const float* __restrict__ fc1,  const float* __restrict__ a1W,
    const float* __restrict__ a1s,  const float* __restrict__ a1b)
{
    extern __shared__ float sm[];
    float* fc1T = sm;            // [cin*64 + o]
    float* a1T  = sm + 4096;     // [cin*32 + o]
    float* s1v  = sm + 6144;
    float* b1v  = sm + 6176;
    float* xball= sm + 6208;

    int tid = threadIdx.x;
    for (int i = tid; i < DD*DD; i += 256) { int o = i>>6, c = i&63; fc1T[c*DD + o] = fc1[i]; }
    for (int i = tid; i < D2*DD; i += 256) { int o = i>>6, c = i&63; a1T[c*D2 + o] = a1W[i]; }
    if (tid < 32) { s1v[tid] = a1s[tid]; b1v[tid] = a1b[tid]; }
    __syncthreads();

    int lane = tid & 31, w = tid >> 5;
    float* xw = xball + w*(DD*ST);
    float w10[10];
    #pragma unroll
    for (int j = 0; j < 10; j++) w10[j] = bb1W[lane*10 + j];
    float bs = bb1s[lane], bbv = bb1b[lane];

    int warpId = blockIdx.x*WPB + w;
    int nwarps = gridDim.x*WPB;
    for (int p = warpId; p < P_TOT; p += nwarps) {
        int b = p >> 14, n = p & (NPTS-1);
        const float* xyzB = xyz + (size_t)b*NPTS*3;
        const float* fpcB = g_fpc + (size_t)b*NPTS*CIN;

        int ids[16]; float fx[16], fn[16];
        bb1_compute(xyzB, n, nidx + (size_t)p*KNN, w10, bs, bbv, ids, fx);
        #pragma unroll
        for (int k = 0; k < 16; k++) fn[k] = fpcB[(size_t)ids[k]*CIN + lane];

        // write concat tile: rows [0..31]=fn (gathered), [32..63]=fx (bb1)
        float4* xr0 = (float4*)&xw[lane*ST];
        float4* xr1 = (float4*)&xw[(lane+32)*ST];
        #pragma unroll
        for (int q = 0; q < 4; q++) {
            xr0[q] = make_float4(fn[4*q], fn[4*q+1], fn[4*q+2], fn[4*q+3]);
            xr1[q] = make_float4(fx[4*q], fx[4*q+1], fx[4*q+2], fx[4*q+3]);
        }
        __syncwarp();

        // attention logits: rows (lane) and (lane+32) of fc1 @ x
        float att0[16], att1[16];
        #pragma unroll
        for (int k = 0; k < 16; k++) { att0[k] = 0.f; att1[k] = 0.f; }
        #pragma unroll 8
        for (int cc = 0; cc < DD; cc++) {
            float w0 = fc1T[cc*DD + lane];
            float w1 = fc1T[cc*DD + lane + 32];
            const float4* xv = (const float4*)&xw[cc*ST];
            #pragma unroll
            for (int q = 0; q < 4; q++) {
                float4 v = xv[q];
                att0[4*q]   += w0*v.x; att0[4*q+1] += w0*v.y;
                att0[4*q+2] += w0*v.z; att0[4*q+3] += w0*v.w;
                att1[4*q]   += w1*v.x; att1[4*q+1] += w1*v.y;
                att1[4*q+2] += w1*v.z; att1[4*q+3] += w1*v.w;
            }
        }
        float agg0 = softagg(att0, fn);
        float agg1 = softagg(att1, fx);
        __syncwarp();
        xw[lane] = agg0; xw[lane+32] = agg1;
        __syncwarp();

        float acc = 0.f;
        #pragma unroll
        for (int cc = 0; cc < DD; cc++) acc += a1T[cc*D2 + lane] * xw[cc];
        g_fagg[(size_t)p*D2 + lane] = fmaxf(acc*s1v[lane] + b1v[lane], 0.f);
        __syncwarp();
    }
}

// ============================================================
// Kernel C: stage-2 attention + mlp2 + shortcut + leaky relu -> g_tmp [B,N,128]
// dyn smem layout (floats):
//  bb2T 0..1024 | fc2T 1024..5120 | a2T 5120..9216 | m2T 9216..17408 |
//  scT 17408..21504 | a2s 21504 | a2b 21568 | m2s 21632 | m2b 21760 |
//  scs 21888 | scb 22016 | xb 22144..(+WPB*64*ST)
// ============================================================
#define SMEM_C_FLOATS (22144 + WPB*DD*ST)

__global__ void __launch_bounds__(256) kC(
    const float* __restrict__ xyz, const int* __restrict__ nidx,
    const float* __restrict__ bb1W, const float* __restrict__ bb1s, const float* __restrict__ bb1b,
    const float* __restrict__ bb2W, const float* __restrict__ bb2s, const float* __restrict__ bb2b,
    const float* __restrict__ fc2,  const float* __restrict__ a2W,
    const float* __restrict__ a2s,  const float* __restrict__ a2b,
    const float* __restrict__ m2W,  const float* __restrict__ m2s, const float* __restrict__ m2b,
    const float* __restrict__ scW,  const float* __restrict__ scs, const float* __restrict__ scb)
{
    extern __shared__ float sm[];
    float* bb2T = sm;             // [j*32 + c]
    float* fc2T = sm + 1024;      // [cin*64 + o]
    float* a2T  = sm + 5120;      // [cin*64 + o]
    float* m2T  = sm + 9216;      // [cin*128 + o]
    float* scT  = sm + 17408;     // [j*128 + o]
    float* a2sv = sm + 21504;
    float* a2bv = sm + 21568;
    float* m2sv = sm + 21632;
    float* m2bv = sm + 21760;
    float* scsv = sm + 21888;
    float* scbv = sm + 22016;
    float* xball= sm + 22144;

    int tid = threadIdx.x;
    for (int i = tid; i < D2*D2; i += 256) { int c = i>>5, j = i&31; bb2T[j*D2 + c] = bb2W[i]; }
    for (int i = tid; i < DD*DD; i += 256) { int o = i>>6, c = i&63; fc2T[c*DD + o] = fc2[i]; }
    for (int i = tid; i < DD*DD; i += 256) { int o = i>>6, c = i&63; a2T[c*DD + o] = a2W[i]; }
    for (int i = tid; i < DOUT*DD; i += 256) { int o = i>>6, c = i&63; m2T[c*DOUT + o] = m2W[i]; }
    for (int i = tid; i < DOUT*D2; i += 256) { int o = i>>5, j = i&31; scT[j*DOUT + o] = scW[i]; }
    for (int i = tid; i < DD; i += 256)   { a2sv[i] = a2s[i]; a2bv[i] = a2b[i]; }
    for (int i = tid; i < DOUT; i += 256) { m2sv[i] = m2s[i]; m2bv[i] = m2b[i];
                                            scsv[i] = scs[i]; scbv[i] = scb[i]; }
    __syncthreads();

    int lane = tid & 31, w = tid >> 5;
    float* xw = xball + w*(DD*ST);
    float w10[10];
    #pragma unroll
    for (int j = 0; j < 10; j++) w10[j] = bb1W[lane*10 + j];
    float bs1 = bb1s[lane], bb1v = bb1b[lane];
    float bs2 = bb2s[lane], bb2v = bb2b[lane];

    int warpId = blockIdx.x*WPB + w;
    int nwarps = gridDim.x*WPB;
    for (int p = warpId; p < P_TOT; p += nwarps) {
        int b = p >> 14, n = p & (NPTS-1);
        const float* xyzB = xyz + (size_t)b*NPTS*3;
        const float* faggB = g_fagg + (size_t)b*NPTS*D2;

        int ids[16]; float fxr[16];
        bb1_compute(xyzB, n, nidx + (size_t)p*KNN, w10, bs1, bb1v, ids, fxr);

        // stage bb1 output into x rows [0..31] for cross-channel bb2
        float4* xr0 = (float4*)&xw[lane*ST];
        #pragma unroll
        for (int q = 0; q < 4; q++)
            xr0[q] = make_float4(fxr[4*q], fxr[4*q+1], fxr[4*q+2], fxr[4*q+3]);
        __syncwarp();

        float fx2[16];
        #pragma unroll
        for (int k = 0; k < 16; k++) fx2[k] = 0.f;
        #pragma unroll 8
        for (int j = 0; j < D2; j++) {
            float wj = bb2T[j*D2 + lane];
            const float4* xv = (const float4*)&xw[j*ST];
            #pragma unroll
            for (int q = 0; q < 4; q++) {
                float4 v = xv[q];
                fx2[4*q]   += wj*v.x; fx2[4*q+1] += wj*v.y;
                fx2[4*q+2] += wj*v.z; fx2[4*q+3] += wj*v.w;
            }
        }
        #pragma unroll
        for (int k = 0; k < 16; k++) fx2[k] = fmaxf(fx2[k]*bs2 + bb2v, 0.f);

        float fn[16];
        #pragma unroll
        for (int k = 0; k < 16; k++) fn[k] = faggB[(size_t)ids[k]*D2 + lane];
        __syncwarp();   // everyone done reading x rows [0..31]

        // concat tile: rows [0..31]=fn (gathered f_agg), [32..63]=fx2
        float4* xr1 = (float4*)&xw[(lane+32)*ST];
        #pragma unroll
        for (int q = 0; q < 4; q++) {
            xr0[q] = make_float4(fn[4*q], fn[4*q+1], fn[4*q+2], fn[4*q+3]);
            xr1[q] = make_float4(fx2[4*q], fx2[4*q+1], fx2[4*q+2], fx2[4*q+3]);
        }
        __syncwarp();

        float att0[16], att1[16];
        #pragma unroll
        for (int k = 0; k < 16; k++) { att0[k] = 0.f; att1[k] = 0.f; }
        #pragma unroll 8
        for (int cc = 0; cc < DD; cc++) {
            float w0 = fc2T[cc*DD + lane];
            float w1 = fc2T[cc*DD + lane + 32];
            const float4* xv = (const float4*)&xw[cc*ST];
            #pragma unroll
            for (int q = 0; q < 4; q++) {
                float4 v = xv[q];
                att0[4*q]   += w0*v.x; att0[4*q+1] += w0*v.y;
                att0[4*q+2] += w0*v.z; att0[4*q+3] += w0*v.w;
                att1[4*q]   += w1*v.x; att1[4*q+1] += w1*v.y;
                att1[4*q+2] += w1*v.z; att1[4*q+3] += w1*v.w;
            }
        }
        float agg0 = softagg(att0, fn);
        float agg1 = softagg(att1, fx2);
        __syncwarp();
        xw[lane] = agg0; xw[lane+32] = agg1;
        __syncwarp();

        // lfa = relu((att2_W @ agg)*s + b), 64 outputs -> xw[64..127]
        #pragma unroll
        for (int h = 0; h < 2; h++) {
            int o = lane + 32*h;
            float acc = 0.f;
            #pragma unroll
            for (int cc = 0; cc < DD; cc++) acc += a2T[cc*DD + o] * xw[cc];
            xw[64 + o] = fmaxf(acc*a2sv[o] + a2bv[o], 0.f);
        }
        // feature column for shortcut -> xw[128..159]
        xw[128 + lane] = g_featT[(size_t)p*CIN + lane];
        __syncwarp();

        // out = leaky_relu(mlp2(lfa) + sc(feature))
        float* outp = g_tmp + (size_t)p*DOUT;
        #pragma unroll
        for (int m = 0; m < 4; m++) {
            int o = lane + 32*m;
            float a = 0.f;
            #pragma unroll
            for (int cc = 0; cc < DD; cc++) a += m2T[cc*DOUT + o] * xw[64 + cc];
            a = a*m2sv[o] + m2bv[o];
            float sc = 0.f;
            #pragma unroll
            for (int j = 0; j < D2; j++) sc += scT[j*DOUT + o] * xw[128 + j];
            sc = sc*scsv[o] + scbv[o];
            float v = a + sc;
            outp[o] = v > 0.f ? v : 0.2f*v;
        }
        __syncwarp();
    }
}

// ============================================================
// Kernel D: transpose g_tmp [B,N,128] -> out [B,128,N]
// ============================================================
__global__ void __launch_bounds__(256) kD(float* __restrict__ out)
{
    __shared__ float tile[32][33];
    int b = blockIdx.z;
    int o0 = blockIdx.y * 32;
    int n0 = blockIdx.x * 32;
    int tx = threadIdx.x, ty = threadIdx.y;
    #pragma unroll
    for (int i = 0; i < 32; i += 8)
        tile[ty+i][tx] = g_tmp[((size_t)b*NPTS + n0 + ty + i)*DOUT + o0 + tx];
    __syncthreads();
    #pragma unroll
    for (int i = 0; i < 32; i += 8)
        out[((size_t)b*DOUT + o0 + ty + i)*NPTS + n0 + tx] = tile[tx][ty+i];
}

// ============================================================
extern "C" void kernel_launch(void* const* d_in, const int* in_sizes, int n_in,
                              void* d_out, int out_size)
{
    const float* feature = (const float*)d_in[0];
    const float* xyz     = (const float*)d_in[1];
    const int*   nidx    = (const int*)  d_in[2];
    const float* mlp1W = (const float*)d_in[3];
    const float* mlp1s = (const float*)d_in[4];
    const float* mlp1b = (const float*)d_in[5];
    const float* bb1W  = (const float*)d_in[6];
    const float* bb1s  = (const float*)d_in[7];
    const float* bb1b  = (const float*)d_in[8];
    const float* fc1   = (const float*)d_in[9];
    const float* a1W   = (const float*)d_in[10];
    const float* a1s   = (const float*)d_in[11];
    const float* a1b   = (const float*)d_in[12];
    const float* bb2W  = (const float*)d_in[13];
    const float* bb2s  = (const float*)d_in[14];
    const float* bb2b  = (const float*)d_in[15];
    const float* fc2   = (const float*)d_in[16];
    const float* a2W   = (const float*)d_in[17];
    const float* a2s   = (const float*)d_in[18];
    const float* a2b   = (const float*)d_in[19];
    const float* m2W   = (const float*)d_in[20];
    const float* m2s   = (const float*)d_in[21];
    const float* m2b   = (const float*)d_in[22];
    const float* scW   = (const float*)d_in[23];
    const float* scs   = (const float*)d_in[24];
    const float* scb   = (const float*)d_in[25];
    float* out = (float*)d_out;

    size_t smB = SMEM_B_FLOATS * sizeof(float);
    size_t smC = SMEM_C_FLOATS * sizeof(float);
    cudaFuncSetAttribute(kB, cudaFuncAttributeMaxDynamicSharedMemorySize, (int)smB);
    cudaFuncSetAttribute(kC, cudaFuncAttributeMaxDynamicSharedMemorySize, (int)smC);

    kA<<<1024, 256>>>(feature, mlp1W, mlp1s, mlp1b);
    kB<<<444, 256, smB>>>(xyz, nidx, bb1W, bb1s, bb1b, fc1, a1W, a1s, a1b);
    kC<<<296, 256, smC>>>(xyz, nidx, bb1W, bb1s, bb1b, bb2W, bb2s, bb2b,
                          fc2, a2W, a2s, a2b, m2W, m2s, m2b, scW, scs, scb);
    kD<<<dim3(NPTS/32, DOUT/32, BATCH), dim3(32, 8)>>>(out);
}

// round 4
// speedup vs baseline: 1.2185x; 1.2185x over previous
#include <cuda_runtime.h>

#define BATCH 4
#define NPTS  16384
#define KNN   16
#define CIN   32
#define D2    32
#define DD    64
#define DOUT  128
#define P_TOT (BATCH*NPTS)
#define ST    20   // x-tile row stride in floats (80B rows: 16B aligned)
#define WPB   8

typedef unsigned long long u64;

__device__ __forceinline__ u64 fma2(u64 a, u64 b, u64 c){
    u64 d; asm("fma.rn.f32x2 %0, %1, %2, %3;" : "=l"(d) : "l"(a), "l"(b), "l"(c)); return d;
}
__device__ __forceinline__ float2 unpk(u64 v){
    float2 f; asm("mov.b64 {%0, %1}, %2;" : "=f"(f.x), "=f"(f.y) : "l"(v)); return f;
}
__device__ __forceinline__ u64 pck(float x, float y){
    u64 v; asm("mov.b64 %0, {%1, %2};" : "=l"(v) : "f"(x), "f"(y)); return v;
}

// ---- scratch ----
__device__ float g_fpc  [P_TOT*CIN];           // [B,N,32]
__device__ float g_featT[P_TOT*CIN];           // [B,N,32]
__device__ float g_fagg [P_TOT*D2];            // [B,N,32]
__device__ float g_lfa  [P_TOT*DD];            // [B,N,64]
__device__ float g_tmp  [(size_t)P_TOT*DOUT];  // [B,N,128]

// ============================================================
// Kernel A: tiled transpose + mlp1.  Coalesced in and out.
// ============================================================
__global__ void __launch_bounds__(256) kA(const float* __restrict__ feature,
                                          const float* __restrict__ W,
                                          const float* __restrict__ s,
                                          const float* __restrict__ bvec)
{
    __shared__ float Wt[CIN*CIN];       // Wt[j*32+o]
    __shared__ float sv[CIN], bv[CIN];
    __shared__ float tile[CIN][33];     // [channel][point]
    __shared__ float otile[CIN][33];    // [outch][point]
    int tx = threadIdx.x, ty = threadIdx.y;
    int tid = ty*32 + tx;
    for (int i = tid; i < CIN*CIN; i += 256) { int o = i>>5, j = i&31; Wt[j*CIN+o] = W[i]; }
    if (ty == 0) { sv[tx] = s[tx]; bv[tx] = bvec[tx]; }

    int t = blockIdx.x;
    int b = t >> 9;
    int n0 = (t & 511) << 5;
    const float* fB = feature + (size_t)b*CIN*NPTS;
    #pragma unroll
    for (int i = 0; i < 32; i += 8)
        tile[ty+i][tx] = fB[(size_t)(ty+i)*NPTS + n0 + tx];
    __syncthreads();

    #pragma unroll
    for (int q = 0; q < 4; q++) {
        int o = ty + 8*q;
        float acc = 0.f;
        #pragma unroll
        for (int j = 0; j < CIN; j++) acc += Wt[j*CIN+o] * tile[j][tx];
        otile[o][tx] = fmaxf(acc*sv[o] + bv[o], 0.f);
    }
    __syncthreads();

    size_t pbase = (size_t)b*NPTS + n0;
    #pragma unroll
    for (int i = 0; i < 32; i += 8) {
        int r = ty + i;
        g_fpc  [(pbase + r)*CIN + tx] = otile[tx][r];
        g_featT[(pbase + r)*CIN + tx] = tile [tx][r];
    }
}

// softmax over 16 + weighted aggregate
__device__ __forceinline__ float softagg(const float* a, const float* v) {
    float m = a[0];
    #pragma unroll
    for (int k = 1; k < 16; k++) m = fmaxf(m, a[k]);
    float se = 0.f, r = 0.f;
    #pragma unroll
    for (int k = 0; k < 16; k++) {
        float e = __expf(a[k] - m);
        se += e; r += e * v[k];
    }
    return r / se;
}

__device__ __forceinline__ void bb1_compute(const float* __restrict__ xyzB, int n,
                                            const int* __restrict__ ip,
                                            const float* w10, float bs, float bbv,
                                            int* ids, float* fx)
{
    int4 i0 = ((const int4*)ip)[0];
    int4 i1 = ((const int4*)ip)[1];
    int4 i2 = ((const int4*)ip)[2];
    int4 i3 = ((const int4*)ip)[3];
    ids[0]=i0.x; ids[1]=i0.y; ids[2]=i0.z; ids[3]=i0.w;
    ids[4]=i1.x; ids[5]=i1.y; ids[6]=i1.z; ids[7]=i1.w;
    ids[8]=i2.x; ids[9]=i2.y; ids[10]=i2.z; ids[11]=i2.w;
    ids[12]=i3.x; ids[13]=i3.y; ids[14]=i3.z; ids[15]=i3.w;
    float cx = xyzB[n*3], cy = xyzB[n*3+1], cz = xyzB[n*3+2];
    float cpart = w10[4]*cx + w10[5]*cy + w10[6]*cz;
    #pragma unroll
    for (int k = 0; k < 16; k++) {
        int id = ids[k];
        float nx = xyzB[id*3], ny = xyzB[id*3+1], nz = xyzB[id*3+2];
        float rx = cx-nx, ry = cy-ny, rz = cz-nz;
        float d = sqrtf(rx*rx + ry*ry + rz*rz);
        float acc = cpart
                  + w10[0]*d  + w10[1]*rx + w10[2]*ry + w10[3]*rz
                  + w10[7]*nx + w10[8]*ny + w10[9]*nz;
        fx[k] = fmaxf(acc*bs + bbv, 0.f);
    }
}

// attention logits for rows (lane, lane+32), packed over k-pairs
__device__ __forceinline__ void att_logits(const float* __restrict__ wdup,
                                           const float* __restrict__ xw, int lane,
                                           float* att0, float* att1)
{
    u64 acc0[8], acc1[8];
    #pragma unroll
    for (int q = 0; q < 8; q++) { acc0[q] = 0ull; acc1[q] = 0ull; }
    #pragma unroll 4
    for (int cc = 0; cc < DD; cc++) {
        u64 w0 = *(const u64*)&wdup[cc*128 + lane*2];
        u64 w1 = *(const u64*)&wdup[cc*128 + (lane+32)*2];
        const ulonglong2* xv = (const ulonglong2*)&xw[cc*ST];
        #pragma unroll
        for (int q = 0; q < 4; q++) {
            ulonglong2 v = xv[q];
            acc0[2*q]   = fma2(w0, v.x, acc0[2*q]);
            acc0[2*q+1] = fma2(w0, v.y, acc0[2*q+1]);
            acc1[2*q]   = fma2(w1, v.x, acc1[2*q]);
            acc1[2*q+1] = fma2(w1, v.y, acc1[2*q+1]);
        }
    }
    #pragma unroll
    for (int q = 0; q < 8; q++) {
        float2 t0 = unpk(acc0[q]); att0[2*q] = t0.x; att0[2*q+1] = t0.y;
        float2 t1 = unpk(acc1[q]); att1[2*q] = t1.x; att1[2*q+1] = t1.y;
    }
}

// ============================================================
// Kernel B: stage-1 attention pooling -> g_fagg [B,N,32]
// smem floats: fc1P[8192] | a1P[2048] | s1v[32] | b1v[32] | x[WPB*1280]
// total 82.2 KB -> 2 blocks/SM
// ============================================================
#define SMEM_B_FLOATS (8192 + 2048 + 32 + 32 + WPB*DD*ST)

__global__ void __launch_bounds__(256) kB(
    const float* __restrict__ xyz, const int* __restrict__ nidx,
    const float* __restrict__ bb1W, const float* __restrict__ bb1s, const float* __restrict__ bb1b,
    const float* __restrict__ fc1,  const float* __restrict__ a1W,
    const float* __restrict__ a1s,  const float* __restrict__ a1b)
{
    extern __shared__ float sm[];
    float* fc1P = sm;            // [cc*128 + o*2 + h]  duplicated broadcast
    float* a1P  = sm + 8192;     // [cc2*64 + o*2 + h]  cc-pairs
    float* s1v  = sm + 10240;
    float* b1v  = sm + 10272;
    float* xball= sm + 10304;

    int tid = threadIdx.x;
    for (int i = tid; i < 8192; i += 256) { int cc = i>>7, o = (i&127)>>1; fc1P[i] = fc1[o*DD + cc]; }
    for (int i = tid; i < 2048; i += 256) { int cc2 = i>>6, r = i&63; int o = r>>1, h = r&1;
                                            a1P[i] = a1W[o*DD + 2*cc2 + h]; }
    if (tid < 32) { s1v[tid] = a1s[tid]; b1v[tid] = a1b[tid]; }
    __syncthreads();

    int lane = tid & 31, w = tid >> 5;
    float* xw = xball + w*(DD*ST);
    float w10[10];
    #pragma unroll
    for (int j = 0; j < 10; j++) w10[j] = bb1W[lane*10 + j];
    float bs = bb1s[lane], bbv = bb1b[lane];

    int warpId = blockIdx.x*WPB + w;
    int nwarps = gridDim.x*WPB;
    for (int p = warpId; p < P_TOT; p += nwarps) {
        int b = p >> 14, n = p & (NPTS-1);
        const float* xyzB = xyz + (size_t)b*NPTS*3;
        const float* fpcB = g_fpc + (size_t)b*NPTS*CIN;

        int ids[16]; float fx[16], fn[16];
        bb1_compute(xyzB, n, nidx + (size_t)p*KNN, w10, bs, bbv, ids, fx);
        #pragma unroll
        for (int k = 0; k < 16; k++) fn[k] = fpcB[(size_t)ids[k]*CIN + lane];

        float4* xr0 = (float4*)&xw[lane*ST];
        float4* xr1 = (float4*)&xw[(lane+32)*ST];
        #pragma unroll
        for (int q = 0; q < 4; q++) {
            xr0[q] = make_float4(fn[4*q], fn[4*q+1], fn[4*q+2], fn[4*q+3]);
            xr1[q] = make_float4(fx[4*q], fx[4*q+1], fx[4*q+2], fx[4*q+3]);
        }
        __syncwarp();

        float att0[16], att1[16];
        att_logits(fc1P, xw, lane, att0, att1);

        float agg0 = softagg(att0, fn);
        float agg1 = softagg(att1, fx);
        __syncwarp();
        xw[lane] = agg0; xw[lane+32] = agg1;
        __syncwarp();

        u64 acc = 0ull;
        #pragma unroll
        for (int cc2 = 0; cc2 < 32; cc2++)
            acc = fma2(*(const u64*)&a1P[cc2*64 + lane*2], *(const u64*)&xw[2*cc2], acc);
        float2 t = unpk(acc);
        g_fagg[(size_t)p*D2 + lane] = fmaxf((t.x + t.y)*s1v[lane] + b1v[lane], 0.f);
        __syncwarp();
    }
}

// ============================================================
// Kernel C1: stage-2 attention -> g_lfa [B,N,64]
// smem floats: bb2T[1024] | fc2P[8192] | a2P[8192] | a2s[64] | a2b[64] | x[WPB*1280]
// total 27776 floats = 111.1 KB -> 2 blocks/SM (fits 227 KB)
// ============================================================
#define SMEM_C1_FLOATS (1024 + 8192 + 8192 + 64 + 64 + WPB*DD*ST)

__global__ void __launch_bounds__(256) kC1(
    const float* __restrict__ xyz, const int* __restrict__ nidx,
    const float* __restrict__ bb1W, const float* __restrict__ bb1s, const float* __restrict__ bb1b,
    const float* __restrict__ bb2W, const float* __restrict__ bb2s, const float* __restrict__ bb2b,
    const float* __restrict__ fc2,  const float* __restrict__ a2W,
    const float* __restrict__ a2s,  const float* __restrict__ a2b)
{
    extern __shared__ float sm[];
    float* bb2T = sm;             // [j*32 + c]  compact transposed
    float* fc2P = sm + 1024;      // [cc*128 + o*2 + h] duplicated broadcast
    float* a2P  = sm + 9216;      // [cc2*128 + o*2 + h] cc-pairs
    float* a2sv = sm + 17408;
    float* a2bv = sm + 17472;
    float* xball= sm + 17536;

    int tid = threadIdx.x;
    for (int i = tid; i < 1024; i += 256) { int c = i>>5, j = i&31; bb2T[j*D2 + c] = bb2W[i]; }
    for (int i = tid; i < 8192; i += 256) { int cc = i>>7, o = (i&127)>>1; fc2P[i] = fc2[o*DD + cc]; }
    for (int i = tid; i < 8192; i += 256) { int cc2 = i>>7, r = i&127; int o = r>>1, h = r&1;
                                            a2P[i] = a2W[o*DD + 2*cc2 + h]; }
    for (int i = tid; i < DD; i += 256) { a2sv[i] = a2s[i]; a2bv[i] = a2b[i]; }
    __syncthreads();

    int lane = tid & 31, w = tid >> 5;
    float* xw = xball + w*(DD*ST);
    float w10[10];
    #pragma unroll
    for (int j = 0; j < 10; j++) w10[j] = bb1W[lane*10 + j];
    float bs1 = bb1s[lane], bb1v = bb1b[lane];
    float bs2 = bb2s[lane], bb2v = bb2b[lane];

    int warpId = blockIdx.x*WPB + w;
    int nwarps = gridDim.x*WPB;
    for (int p = warpId; p < P_TOT; p += nwarps) {
        int b = p >> 14, n = p & (NPTS-1);
        const float* xyzB = xyz + (size_t)b*NPTS*3;
        const float* faggB = g_fagg + (size_t)b*NPTS*D2;

        int ids[16]; float fxr[16];
        bb1_compute(xyzB, n, nidx + (size_t)p*KNN, w10, bs1, bb1v, ids, fxr);

        float4* xr0 = (float4*)&xw[lane*ST];
        #pragma unroll
        for (int q = 0; q < 4; q++)
            xr0[q] = make_float4(fxr[4*q], fxr[4*q+1], fxr[4*q+2], fxr[4*q+3]);

        // issue gather early to hide L2 latency behind bb2 math
        float fn[16];
        #pragma unroll
        for (int k = 0; k < 16; k++) fn[k] = faggB[(size_t)ids[k]*D2 + lane];
        __syncwarp();

        // bb2: fx2 = relu(bb2W @ fx), packed over k-pairs
        u64 accx[8];
        #pragma unroll
        for (int q = 0; q < 8; q++) accx[q] = 0ull;
        #pragma unroll 4
        for (int j = 0; j < D2; j++) {
            float wv = bb2T[j*D2 + lane];
            u64 wj = pck(wv, wv);
            const ulonglong2* xv = (const ulonglong2*)&xw[j*ST];
            #pragma unroll
            for (int q = 0; q < 4; q++) {
                ulonglong2 v = xv[q];
                accx[2*q]   = fma2(wj, v.x, accx[2*q]);
                accx[2*q+1] = fma2(wj, v.y, accx[2*q+1]);
            }
        }
        float fx2[16];
        #pragma unroll
        for (int q = 0; q < 8; q++) {
            float2 t = unpk(accx[q]);
            fx2[2*q]   = fmaxf(t.x*bs2 + bb2v, 0.f);
            fx2[2*q+1] = fmaxf(t.y*bs2 + bb2v, 0.f);
        }
        __syncwarp();

        float4* xr1 = (float4*)&xw[(lane+32)*ST];
        #pragma unroll
        for (int q = 0; q < 4; q++) {
            xr0[q] = make_float4(fn[4*q], fn[4*q+1], fn[4*q+2], fn[4*q+3]);
            xr1[q] = make_float4(fx2[4*q], fx2[4*q+1], fx2[4*q+2], fx2[4*q+3]);
        }
        __syncwarp();

        float att0[16], att1[16];
        att_logits(fc2P, xw, lane, att0, att1);

        float agg0 = softagg(att0, fn);
        float agg1 = softagg(att1, fx2);
        __syncwarp();
        xw[lane] = agg0; xw[lane+32] = agg1;
        __syncwarp();

        // lfa = relu((a2W @ agg)*s + b), 64 outputs (lane, lane+32)
        u64 aA = 0ull, aB = 0ull;
        #pragma unroll
        for (int cc2 = 0; cc2 < 32; cc2++) {
            u64 xp = *(const u64*)&xw[2*cc2];
            aA = fma2(*(const u64*)&a2P[cc2*128 + lane*2], xp, aA);
            aB = fma2(*(const u64*)&a2P[cc2*128 + (lane+32)*2], xp, aB);
        }
        float2 tA = unpk(aA), tB = unpk(aB);
        float* lp = g_lfa + (size_t)p*DD;
        lp[lane]      = fmaxf((tA.x + tA.y)*a2sv[lane]      + a2bv[lane],      0.f);
        lp[lane + 32] = fmaxf((tB.x + tB.y)*a2sv[lane + 32] + a2bv[lane + 32], 0.f);
        __syncwarp();
    }
}

// ============================================================
// Kernel C2: mlp2 + shortcut + leaky relu -> g_tmp [B,N,128]
// ============================================================
#define SMEM_C2_FLOATS (8192 + 4096 + 512 + WPB*96)

__global__ void __launch_bounds__(256) kC2(
    const float* __restrict__ m2W, const float* __restrict__ m2s, const float* __restrict__ m2b,
    const float* __restrict__ scW, const float* __restrict__ scs, const float* __restrict__ scb)
{
    extern __shared__ float sm[];
    float* m2P  = sm;          // [cc2*256 + o*2 + h]
    float* scP  = sm + 8192;   // [j2*256 + o*2 + h]
    float* m2sv = sm + 12288;
    float* m2bv = sm + 12416;
    float* scsv = sm + 12544;
    float* scbv = sm + 12672;
    float* sbuf = sm + 12800;

    int tid = threadIdx.x;
    for (int i = tid; i < 8192; i += 256) { int cc2 = i>>8, r = i&255; int o = r>>1, h = r&1;
                                            m2P[i] = m2W[o*DD + 2*cc2 + h]; }
    for (int i = tid; i < 4096; i += 256) { int j2 = i>>8, r = i&255; int o = r>>1, h = r&1;
                                            scP[i] = scW[o*D2 + 2*j2 + h]; }
    for (int i = tid; i < DOUT; i += 256) { m2sv[i] = m2s[i]; m2bv[i] = m2b[i];
                                            scsv[i] = scs[i]; scbv[i] = scb[i]; }
    __syncthreads();

    int lane = tid & 31, w = tid >> 5;
    float* sb = sbuf + w*96;
    int warpId = blockIdx.x*WPB + w;
    int nwarps = gridDim.x*WPB;
    for (int p = warpId; p < P_TOT; p += nwarps) {
        sb[lane]      = g_lfa[(size_t)p*DD + lane];
        sb[32 + lane] = g_lfa[(size_t)p*DD + 32 + lane];
        sb[64 + lane] = g_featT[(size_t)p*CIN + lane];
        __syncwarp();
        float* outp = g_tmp + (size_t)p*DOUT;
        #pragma unroll
        for (int m = 0; m < 4; m++) {
            int o = lane + 32*m;
            u64 acc = 0ull;
            #pragma unroll
            for (int cc2 = 0; cc2 < 32; cc2++)
                acc = fma2(*(const u64*)&m2P[cc2*256 + o*2], *(const u64*)&sb[2*cc2], acc);
            float2 t = unpk(acc);
            float a = (t.x + t.y)*m2sv[o] + m2bv[o];
            u64 acs = 0ull;
            #pragma unroll
            for (int j2 = 0; j2 < 16; j2++)
                acs = fma2(*(const u64*)&scP[j2*256 + o*2], *(const u64*)&sb[64 + 2*j2], acs);
            t = unpk(acs);
            float scv = (t.x + t.y)*scsv[o] + scbv[o];
            float v = a + scv;
            outp[o] = v > 0.f ? v : 0.2f*v;
        }
        __syncwarp();
    }
}

// ============================================================
// Kernel D: transpose g_tmp [B,N,128] -> out [B,128,N]
// ============================================================
__global__ void __launch_bounds__(256) kD(float* __restrict__ out)
{
    __shared__ float tile[32][33];
    int b = blockIdx.z;
    int o0 = blockIdx.y * 32;
    int n0 = blockIdx.x * 32;
    int tx = threadIdx.x, ty = threadIdx.y;
    #pragma unroll
    for (int i = 0; i < 32; i += 8)
        tile[ty+i][tx] = g_tmp[((size_t)b*NPTS + n0 + ty + i)*DOUT + o0 + tx];
    __syncthreads();
    #pragma unroll
    for (int i = 0; i < 32; i += 8)
        out[((size_t)b*DOUT + o0 + ty + i)*NPTS + n0 + tx] = tile[tx][ty+i];
}

// ============================================================
extern "C" void kernel_launch(void* const* d_in, const int* in_sizes, int n_in,
                              void* d_out, int out_size)
{
    const float* feature = (const float*)d_in[0];
    const float* xyz     = (const float*)d_in[1];
    const int*   nidx    = (const int*)  d_in[2];
    const float* mlp1W = (const float*)d_in[3];
    const float* mlp1s = (const float*)d_in[4];
    const float* mlp1b = (const float*)d_in[5];
    const float* bb1W  = (const float*)d_in[6];
    const float* bb1s  = (const float*)d_in[7];
    const float* bb1b  = (const float*)d_in[8];
    const float* fc1   = (const float*)d_in[9];
    const float* a1W   = (const float*)d_in[10];
    const float* a1s   = (const float*)d_in[11];
    const float* a1b   = (const float*)d_in[12];
    const float* bb2W  = (const float*)d_in[13];
    const float* bb2s  = (const float*)d_in[14];
    const float* bb2b  = (const float*)d_in[15];
    const float* fc2   = (const float*)d_in[16];
    const float* a2W   = (const float*)d_in[17];
    const float* a2s   = (const float*)d_in[18];
    const float* a2b   = (const float*)d_in[19];
    const float* m2W   = (const float*)d_in[20];
    const float* m2s   = (const float*)d_in[21];
    const float* m2b   = (const float*)d_in[22];
    const float* scW   = (const float*)d_in[23];
    const float* scs   = (const float*)d_in[24];
    const float* scb   = (const float*)d_in[25];
    float* out = (float*)d_out;

    size_t smB  = SMEM_B_FLOATS  * sizeof(float);
    size_t smC1 = SMEM_C1_FLOATS * sizeof(float);
    size_t smC2 = SMEM_C2_FLOATS * sizeof(float);
    cudaFuncSetAttribute(kB,  cudaFuncAttributeMaxDynamicSharedMemorySize, (int)smB);
    cudaFuncSetAttribute(kC1, cudaFuncAttributeMaxDynamicSharedMemorySize, (int)smC1);
    cudaFuncSetAttribute(kC2, cudaFuncAttributeMaxDynamicSharedMemorySize, (int)smC2);

    kA<<<2048, dim3(32,8)>>>(feature, mlp1W, mlp1s, mlp1b);
    kB<<<296, 256, smB>>>(xyz, nidx, bb1W, bb1s, bb1b, fc1, a1W, a1s, a1b);
    kC1<<<296, 256, smC1>>>(xyz, nidx, bb1W, bb1s, bb1b, bb2W, bb2s, bb2b,
                            fc2, a2W, a2s, a2b);
    kC2<<<592, 256, smC2>>>(m2W, m2s, m2b, scW, scs, scb);
    kD<<<dim3(NPTS/32, DOUT/32, BATCH), dim3(32, 8)>>>(out);
}